// round 8
// baseline (speedup 1.0000x reference)
#include <cuda_runtime.h>
#include <float.h>

#define KMAX   256
#define SEGN   258                  // segment entries: 0..K (K+1 used), padded
#define BMAX   8
#define BINS   4096                 // guide bins; 16 sub-bins each -> 65536 sub-bins
#define SUBS   65536
#define GBLK   16                   // guide build blocks (4096 / 256)
#define GRIDX  38                   // 38 x 8 batches = 304 CTAs = 2/SM on 152 SMs

// Exact segment-index machinery:
//   t(x) = clamp((int)(x*65536f), 0, 65535)  -- exact: *2^16 only shifts exponent
//   g_guide[j] = (cnt << 16) | mask16 : cnt = #knots with t(E) < j*16,
//                mask bit i set iff some knot has t(E) == j*16+i
// Per batch: y = slope[s]*x + offset[s], s = #{k : E[k] <= x}
//   (s=0 low clamp, s=K high clamp); offsets built in double (no cancellation).
__device__ unsigned g_guide[BINS];
__device__ float2   g_seg2[BMAX][SEGN];

// Dynamic smem layout (words):
//   [0,              8256)  slope_b : slope[s] for lane l at s*32+l  (33 KB)
//   [8256,          16512)  off_b   : offset[s] likewise             (33 KB)
//   [16512,         20608)  guide   : packed guide                   (16 KB)
//   [20608,         20864)  E knots                                  ( 1 KB)
#define OFF_SLOPE 0
#define OFF_OFF   (SEGN * 32)
#define OFF_GUIDE (2 * SEGN * 32)
#define OFF_E     (2 * SEGN * 32 + BINS)
#define SMEM_WORDS (2 * SEGN * 32 + BINS + KMAX)

// ---------------------------------------------------------------------------
// Kernel 1 (merged setup). Grid = B + GBLK, 256 threads.
// ---------------------------------------------------------------------------
__global__ void setup_tables(const float* __restrict__ w,    // [B, NB]
                             const float* __restrict__ E,    // [K]
                             const float* __restrict__ f0,   // [K]
                             const float* __restrict__ Hb,   // [K, NB]
                             int K, int NB, int B)
{
    const int blk = blockIdx.x;
    const int tid = threadIdx.x;

    if (blk < B) {
        const int b = blk;
        __shared__ float c[KMAX];
        __shared__ float Es[KMAX];

        if (tid < K) {
            float acc = f0[tid];
            const float* hrow = Hb + (long long)tid * NB;
            const float* wrow = w  + (long long)b   * NB;
            #pragma unroll 5
            for (int n = 0; n < NB; n++)
                acc = fmaf(hrow[n], wrow[n], acc);
            c[tid]  = acc;
            Es[tid] = E[tid];
        }
        __syncthreads();

        if (tid == 0) {
            g_seg2[b][0] = make_float2(0.0f, c[0]);       // x <  E[0]
            g_seg2[b][K] = make_float2(0.0f, c[K - 1]);   // x >= E[K-1]
        }
        if (tid >= 1 && tid <= K - 1) {
            const double e0 = (double)Es[tid - 1], e1 = (double)Es[tid];
            const double sl = ((double)c[tid] - (double)c[tid - 1]) / (e1 - e0);
            const double of = (double)c[tid - 1] - sl * e0;
            g_seg2[b][tid] = make_float2((float)sl, (float)of);
        }
    } else {
        __shared__ int tE[KMAX];
        for (int k = tid; k < K; k += 256) {
            int t = (int)(E[k] * 65536.0f);               // exact
            tE[k] = min(max(t, 0), SUBS - 1);
        }
        __syncthreads();

        const int j = (blk - B) * 256 + tid;
        if (j < BINS) {
            const int lo = j * 16, hi = lo + 16;
            int cnt = 0; unsigned mask = 0u;
            for (int k = 0; k < K; k++) {
                const int t = tE[k];
                cnt += (t < lo);
                if (t >= lo && t < hi) mask |= 1u << (t - lo);
            }
            g_guide[j] = ((unsigned)cnt << 16) | mask;
        }
    }
}

// ---------------------------------------------------------------------------
// Kernel 2: streaming apply. Grid = (GRIDX, B), 256 threads, dynamic smem.
// ---------------------------------------------------------------------------
__device__ __forceinline__ float interp1(float x, int lane,
                                         const unsigned* __restrict__ G,
                                         const float*    __restrict__ SL,
                                         const float*    __restrict__ OF,
                                         const float*    __restrict__ Ek,
                                         int K)
{
    int t = (int)(x * 65536.0f);                          // exact floor for x>=0
    t = min(max(t, 0), SUBS - 1);
    const unsigned e = G[t >> 4];                         // LDS.32, ~3.4 waves
    const int ts = t & 15;
    const unsigned m = e & 0xFFFFu;
    int s = (int)(e >> 16) + __popc(m & ((1u << ts) - 1u));
    if (m & (1u << ts)) {                                 // knot shares sub-bin: ~0.4%/lane
        while (s < K && Ek[s] <= x) ++s;                  // exact resolve
    }
    const int a = s * 32 + lane;                          // bank == lane: conflict-free
    return __saturatef(fmaf(x, SL[a], OF[a]));            // 2x LDS.32, 1 wave each
}

__global__ void __launch_bounds__(256, 2)
tmo_apply(const float* __restrict__ img, float* __restrict__ out,
          const float* __restrict__ E, int npix, int K)
{
    extern __shared__ float smem[];
    float*    SL = smem + OFF_SLOPE;
    float*    OF = smem + OFF_OFF;
    unsigned* G  = (unsigned*)(smem + OFF_GUIDE);
    float*    Ek = smem + OFF_E;

    const int b    = blockIdx.y;
    const int tid  = threadIdx.x;
    const int lane = tid & 31;

    // Fill banked seg copies: warp-uniform s per iteration -> LDG broadcast,
    // STS with bank == lane (coalesced, conflict-free).
    for (int idx = tid; idx < (K + 1) * 32; idx += 256) {
        const int s = idx >> 5, l = idx & 31;
        const float2 v = g_seg2[b][s];
        SL[s * 32 + l] = v.x;
        OF[s * 32 + l] = v.y;
    }
    for (int i = tid; i < BINS; i += 256) G[i] = g_guide[i];
    for (int i = tid; i < K;    i += 256) Ek[i] = E[i];
    __syncthreads();

    const long long base = (long long)b * (long long)npix;
    const float4* __restrict__ in4  = (const float4*)(img + base);
    float4*       __restrict__ out4 = (float4*)(out + base);

    const int n4     = npix >> 2;
    const int stride = GRIDX * 256;
    int i = blockIdx.x * 256 + tid;

    // 8x unrolled: 8 independent LDG.128 in flight (DRAM latency cover at
    // 16 warps/SM), then compute + store.
    for (; i + 7 * stride < n4; i += 8 * stride) {
        float4 xa[8];
        #pragma unroll
        for (int u = 0; u < 8; u++) xa[u] = in4[i + u * stride];
        #pragma unroll
        for (int u = 0; u < 8; u++) {
            float4 y;
            y.x = interp1(xa[u].x, lane, G, SL, OF, Ek, K);
            y.y = interp1(xa[u].y, lane, G, SL, OF, Ek, K);
            y.z = interp1(xa[u].z, lane, G, SL, OF, Ek, K);
            y.w = interp1(xa[u].w, lane, G, SL, OF, Ek, K);
            out4[i + u * stride] = y;
        }
    }
    for (; i < n4; i += stride) {
        const float4 x = in4[i];
        float4 y;
        y.x = interp1(x.x, lane, G, SL, OF, Ek, K);
        y.y = interp1(x.y, lane, G, SL, OF, Ek, K);
        y.z = interp1(x.z, lane, G, SL, OF, Ek, K);
        y.w = interp1(x.w, lane, G, SL, OF, Ek, K);
        out4[i] = y;
    }

    // scalar tail (npix not divisible by 4; empty for this shape)
    if (blockIdx.x == 0) {
        for (int tix = (n4 << 2) + tid; tix < npix; tix += 256)
            out[base + tix] = interp1(img[base + tix], lane, G, SL, OF, Ek, K);
    }
}

// ---------------------------------------------------------------------------
// Inputs (metadata order): hdr_image [B,C,H,W] f32, weights_w [B,NB] f32,
//                          E_samples [K] f32, f0_mean [K] f32, H_basis [K,NB] f32
// Output: [B,C,H,W] f32
// ---------------------------------------------------------------------------
extern "C" void kernel_launch(void* const* d_in, const int* in_sizes, int n_in,
                              void* d_out, int out_size)
{
    const float* img = (const float*)d_in[0];
    const float* w   = (const float*)d_in[1];
    const float* E   = (const float*)d_in[2];
    const float* f0  = (const float*)d_in[3];
    const float* Hb  = (const float*)d_in[4];
    float* out = (float*)d_out;

    const int K    = in_sizes[2];                 // 256
    const int NB   = in_sizes[4] / K;             // 25
    const int B    = in_sizes[1] / NB;            // 8
    const int npix = in_sizes[0] / B;             // C*H*W = 6,220,800

    const size_t smem_bytes = (size_t)SMEM_WORDS * 4;   // 83,456 B
    (void)cudaFuncSetAttribute(tmo_apply,
                               cudaFuncAttributeMaxDynamicSharedMemorySize,
                               (int)smem_bytes);

    setup_tables<<<B + GBLK, 256>>>(w, E, f0, Hb, K, NB, B);

    dim3 grid(GRIDX, B);                          // 304 CTAs = 2/SM
    tmo_apply<<<grid, 256, smem_bytes>>>(img, out, E, npix, K);
}

// round 9
// speedup vs baseline: 1.0023x; 1.0023x over previous
#include <cuda_runtime.h>
#include <float.h>

#define KMAX   256
#define SEGN   258                  // segment entries: 0..K (K+1 used), padded
#define BMAX   8
#define BINS   4096                 // guide bins; 16 sub-bins each -> 65536 sub-bins
#define SUBS   65536
#define GBLK   16                   // guide build blocks (4096 / 256)
#define REP    16                   // seg-table replication degree
#define GRIDX  76                   // 76 x 8 = 608 CTAs = 4/SM on 152 SMs

// Exact segment-index machinery:
//   t(x) = clamp((int)(x*65536f), 0, 65535)  -- exact: *2^16 only shifts exponent
//   g_guide[j] = (cnt << 16) | mask16 : cnt = #knots with t(E) < j*16,
//                mask bit i set iff some knot has t(E) == j*16+i
// Per batch: y = slope[s]*x + offset[s], s = #{k : E[k] <= x}
//   (s=0 low clamp, s=K high clamp); offsets built in double (no cancellation).
__device__ unsigned g_guide[BINS];
__device__ float2   g_seg2[BMAX][SEGN];

// Dynamic smem layout (words):
//   [0,            SEGN*REP)    slope_r : slope[s] at s*REP + (lane&15)  (16.5 KB)
//   [SEGN*REP,   2*SEGN*REP)    off_r   : offset[s] likewise             (16.5 KB)
//   [+0,          +BINS)        guide   : packed popcount guide          (16 KB)
//   [+BINS,       +BINS+KMAX)   E knots                                  ( 1 KB)
#define OFF_SLOPE 0
#define OFF_OFF   (SEGN * REP)
#define OFF_GUIDE (2 * SEGN * REP)
#define OFF_E     (2 * SEGN * REP + BINS)
#define SMEM_WORDS (2 * SEGN * REP + BINS + KMAX)

// ---------------------------------------------------------------------------
// Kernel 1 (merged setup). Grid = B + GBLK, 256 threads.
// ---------------------------------------------------------------------------
__global__ void setup_tables(const float* __restrict__ w,    // [B, NB]
                             const float* __restrict__ E,    // [K]
                             const float* __restrict__ f0,   // [K]
                             const float* __restrict__ Hb,   // [K, NB]
                             int K, int NB, int B)
{
    const int blk = blockIdx.x;
    const int tid = threadIdx.x;

    if (blk < B) {
        const int b = blk;
        __shared__ float c[KMAX];
        __shared__ float Es[KMAX];

        if (tid < K) {
            float acc = f0[tid];
            const float* hrow = Hb + (long long)tid * NB;
            const float* wrow = w  + (long long)b   * NB;
            #pragma unroll 5
            for (int n = 0; n < NB; n++)
                acc = fmaf(hrow[n], wrow[n], acc);
            c[tid]  = acc;
            Es[tid] = E[tid];
        }
        __syncthreads();

        if (tid == 0) {
            g_seg2[b][0] = make_float2(0.0f, c[0]);       // x <  E[0]
            g_seg2[b][K] = make_float2(0.0f, c[K - 1]);   // x >= E[K-1]
        }
        if (tid >= 1 && tid <= K - 1) {
            const double e0 = (double)Es[tid - 1], e1 = (double)Es[tid];
            const double sl = ((double)c[tid] - (double)c[tid - 1]) / (e1 - e0);
            const double of = (double)c[tid - 1] - sl * e0;
            g_seg2[b][tid] = make_float2((float)sl, (float)of);
        }
    } else {
        __shared__ int tE[KMAX];
        for (int k = tid; k < K; k += 256) {
            int t = (int)(E[k] * 65536.0f);               // exact
            tE[k] = min(max(t, 0), SUBS - 1);
        }
        __syncthreads();

        const int j = (blk - B) * 256 + tid;
        if (j < BINS) {
            const int lo = j * 16, hi = lo + 16;
            int cnt = 0; unsigned mask = 0u;
            for (int k = 0; k < K; k++) {
                const int t = tE[k];
                cnt += (t < lo);
                if (t >= lo && t < hi) mask |= 1u << (t - lo);
            }
            g_guide[j] = ((unsigned)cnt << 16) | mask;
        }
    }
}

// ---------------------------------------------------------------------------
// Kernel 2: streaming apply. Grid = (GRIDX, B), 256 threads, dynamic smem.
// ---------------------------------------------------------------------------
__device__ __forceinline__ float interp1(float x, int l16,
                                         const unsigned* __restrict__ G,
                                         const float*    __restrict__ SL,
                                         const float*    __restrict__ OF,
                                         const float*    __restrict__ Ek,
                                         int K)
{
    int t = (int)(x * 65536.0f);                          // exact floor for x>=0
    t = min(max(t, 0), SUBS - 1);
    const unsigned e = G[t >> 4];                         // LDS.32, ~3.4 waves
    const int ts = t & 15;
    const unsigned m = e & 0xFFFFu;
    int s = (int)(e >> 16) + __popc(m & ((1u << ts) - 1u));
    if (m & (1u << ts)) {                                 // knot shares sub-bin: ~0.4%/lane
        while (s < K && Ek[s] <= x) ++s;                  // exact resolve
    }
    const int a = s * REP + l16;                          // 16-way: ~2 waves per load
    return __saturatef(fmaf(x, SL[a], OF[a]));            // 2x LDS.32
}

__global__ void __launch_bounds__(256, 4)
tmo_apply(const float* __restrict__ img, float* __restrict__ out,
          const float* __restrict__ E, int npix, int K)
{
    extern __shared__ float smem[];
    float*    SL = smem + OFF_SLOPE;
    float*    OF = smem + OFF_OFF;
    unsigned* G  = (unsigned*)(smem + OFF_GUIDE);
    float*    Ek = smem + OFF_E;

    const int b   = blockIdx.y;
    const int tid = threadIdx.x;
    const int l16 = tid & (REP - 1);

    // Fill replicated seg copies: warp-uniform s per iteration -> broadcast LDG,
    // conflict-free STS.
    for (int idx = tid; idx < (K + 1) * REP; idx += 256) {
        const int s = idx / REP, l = idx % REP;
        const float2 v = g_seg2[b][s];
        SL[s * REP + l] = v.x;
        OF[s * REP + l] = v.y;
    }
    for (int i = tid; i < BINS; i += 256) G[i] = g_guide[i];
    for (int i = tid; i < K;    i += 256) Ek[i] = E[i];
    __syncthreads();

    const long long base = (long long)b * (long long)npix;
    const float4* __restrict__ in4  = (const float4*)(img + base);
    float4*       __restrict__ out4 = (float4*)(out + base);

    const int n4     = npix >> 2;
    const int stride = GRIDX * 256;
    int i = blockIdx.x * 256 + tid;

    // 8x unrolled: 8 independent LDG.128 in flight (DRAM latency cover at
    // 32 warps/SM), then compute + store.
    for (; i + 7 * stride < n4; i += 8 * stride) {
        float4 xa[8];
        #pragma unroll
        for (int u = 0; u < 8; u++) xa[u] = in4[i + u * stride];
        #pragma unroll
        for (int u = 0; u < 8; u++) {
            float4 y;
            y.x = interp1(xa[u].x, l16, G, SL, OF, Ek, K);
            y.y = interp1(xa[u].y, l16, G, SL, OF, Ek, K);
            y.z = interp1(xa[u].z, l16, G, SL, OF, Ek, K);
            y.w = interp1(xa[u].w, l16, G, SL, OF, Ek, K);
            out4[i + u * stride] = y;
        }
    }
    for (; i < n4; i += stride) {
        const float4 x = in4[i];
        float4 y;
        y.x = interp1(x.x, l16, G, SL, OF, Ek, K);
        y.y = interp1(x.y, l16, G, SL, OF, Ek, K);
        y.z = interp1(x.z, l16, G, SL, OF, Ek, K);
        y.w = interp1(x.w, l16, G, SL, OF, Ek, K);
        out4[i] = y;
    }

    // scalar tail (npix not divisible by 4; empty for this shape)
    if (blockIdx.x == 0) {
        for (int tix = (n4 << 2) + tid; tix < npix; tix += 256)
            out[base + tix] = interp1(img[base + tix], l16, G, SL, OF, Ek, K);
    }
}

// ---------------------------------------------------------------------------
// Inputs (metadata order): hdr_image [B,C,H,W] f32, weights_w [B,NB] f32,
//                          E_samples [K] f32, f0_mean [K] f32, H_basis [K,NB] f32
// Output: [B,C,H,W] f32
// ---------------------------------------------------------------------------
extern "C" void kernel_launch(void* const* d_in, const int* in_sizes, int n_in,
                              void* d_out, int out_size)
{
    const float* img = (const float*)d_in[0];
    const float* w   = (const float*)d_in[1];
    const float* E   = (const float*)d_in[2];
    const float* f0  = (const float*)d_in[3];
    const float* Hb  = (const float*)d_in[4];
    float* out = (float*)d_out;

    const int K    = in_sizes[2];                 // 256
    const int NB   = in_sizes[4] / K;             // 25
    const int B    = in_sizes[1] / NB;            // 8
    const int npix = in_sizes[0] / B;             // C*H*W = 6,220,800

    const size_t smem_bytes = (size_t)SMEM_WORDS * 4;   // 50,432 B
    (void)cudaFuncSetAttribute(tmo_apply,
                               cudaFuncAttributeMaxDynamicSharedMemorySize,
                               (int)smem_bytes);

    setup_tables<<<B + GBLK, 256>>>(w, E, f0, Hb, K, NB, B);

    dim3 grid(GRIDX, B);                          // 608 CTAs = 4/SM
    tmo_apply<<<grid, 256, smem_bytes>>>(img, out, E, npix, K);
}

// round 11
// speedup vs baseline: 1.0175x; 1.0152x over previous
#include <cuda_runtime.h>
#include <float.h>

#define KMAX   256
#define SEGN   258                  // segment entries: 0..K (K+1 used), padded
#define BMAX   8
#define BINS   2048                 // guide bins; 16 sub-bins each -> 32768 sub-bins
#define SUBS   32768
#define GBLK   8                    // guide build blocks (2048 / 256)
#define REP    8                    // seg-table replication degree
#define GRIDX  152                  // 152 x 8 = 1216 CTAs = 8/SM on 152 SMs

// Exact segment-index machinery:
//   t(x) = clamp((int)(x*32768f), 0, 32767)  -- exact: *2^15 only shifts exponent
//   g_guide[j] = (cnt << 16) | mask16 : cnt = #knots with t(E) < j*16,
//                mask bit i set iff some knot has t(E) == j*16+i
// Per batch: y = slope[s]*x + offset[s], s = #{k : E[k] <= x}
//   (s=0 low clamp, s=K high clamp); offsets built in double (no cancellation).
__device__ unsigned g_guide[BINS];
__device__ float2   g_seg2[BMAX][SEGN];

// Dynamic smem layout (words):
//   [0,           SEGN*REP)   slope_r : slope[s], 8 copies, XOR-selected (8.25 KB)
//   [SEGN*REP,  2*SEGN*REP)   off_r   : offset[s] likewise               (8.25 KB)
//   [+0,         +BINS)       guide   : packed popcount guide            (8 KB)
//   [+BINS,      +BINS+KMAX)  E knots                                    (1 KB)
#define OFF_SLOPE 0
#define OFF_OFF   (SEGN * REP)
#define OFF_GUIDE (2 * SEGN * REP)
#define OFF_E     (2 * SEGN * REP + BINS)
#define SMEM_WORDS (2 * SEGN * REP + BINS + KMAX)   // 6528 words = 25.5 KB

// ---------------------------------------------------------------------------
// Kernel 1 (merged setup). Grid = B + GBLK, 256 threads.
// ---------------------------------------------------------------------------
__global__ void setup_tables(const float* __restrict__ w,    // [B, NB]
                             const float* __restrict__ E,    // [K]
                             const float* __restrict__ f0,   // [K]
                             const float* __restrict__ Hb,   // [K, NB]
                             int K, int NB, int B)
{
    const int blk = blockIdx.x;
    const int tid = threadIdx.x;

    if (blk < B) {
        const int b = blk;
        __shared__ float c[KMAX];
        __shared__ float Es[KMAX];

        if (tid < K) {
            float acc = f0[tid];
            const float* hrow = Hb + (long long)tid * NB;
            const float* wrow = w  + (long long)b   * NB;
            #pragma unroll 5
            for (int n = 0; n < NB; n++)
                acc = fmaf(hrow[n], wrow[n], acc);
            c[tid]  = acc;
            Es[tid] = E[tid];
        }
        __syncthreads();

        if (tid == 0) {
            g_seg2[b][0] = make_float2(0.0f, c[0]);       // x <  E[0]
            g_seg2[b][K] = make_float2(0.0f, c[K - 1]);   // x >= E[K-1]
        }
        if (tid >= 1 && tid <= K - 1) {
            const double e0 = (double)Es[tid - 1], e1 = (double)Es[tid];
            const double sl = ((double)c[tid] - (double)c[tid - 1]) / (e1 - e0);
            const double of = (double)c[tid - 1] - sl * e0;
            g_seg2[b][tid] = make_float2((float)sl, (float)of);
        }
    } else {
        __shared__ int tE[KMAX];
        for (int k = tid; k < K; k += 256) {
            int t = (int)(E[k] * 32768.0f);               // exact
            tE[k] = min(max(t, 0), SUBS - 1);
        }
        __syncthreads();

        const int j = (blk - B) * 256 + tid;
        if (j < BINS) {
            const int lo = j * 16, hi = lo + 16;
            int cnt = 0; unsigned mask = 0u;
            for (int k = 0; k < K; k++) {
                const int t = tE[k];
                cnt += (t < lo);
                if (t >= lo && t < hi) mask |= 1u << (t - lo);
            }
            g_guide[j] = ((unsigned)cnt << 16) | mask;
        }
    }
}

// ---------------------------------------------------------------------------
// Kernel 2: streaming apply. Grid = (GRIDX, B), 256 threads, dynamic smem.
// ---------------------------------------------------------------------------
__device__ __forceinline__ float interp1(float x, int l8,
                                         const unsigned* __restrict__ G,
                                         const float*    __restrict__ SL,
                                         const float*    __restrict__ OF,
                                         const float*    __restrict__ Ek,
                                         int K)
{
    int t = (int)(x * 32768.0f);                          // exact floor for x>=0
    t = min(max(t, 0), SUBS - 1);
    const unsigned e = G[t >> 4];                         // LDS.32, ~3.4 waves
    const int ts = t & 15;
    const unsigned m = e & 0xFFFFu;
    int s = (int)(e >> 16) + __popc(m & ((1u << ts) - 1u));
    if (m & (1u << ts)) {                                 // knot shares sub-bin: ~0.8%/lane
        while (s < K && Ek[s] <= x) ++s;                  // exact resolve
    }
    // XOR copy-selection: any copy j is valid; j = l8 ^ (s&7) scrambles banks so
    // lanes sharing l8 collide only when s&7 matches (~1.6 waves per LDS.32).
    const int a = s * REP + (l8 ^ (s & (REP - 1)));
    return __saturatef(fmaf(x, SL[a], OF[a]));
}

__global__ void __launch_bounds__(256, 8)
tmo_apply(const float* __restrict__ img, float* __restrict__ out,
          const float* __restrict__ E, int npix, int K)
{
    extern __shared__ float smem[];
    float*    SL = smem + OFF_SLOPE;
    float*    OF = smem + OFF_OFF;
    unsigned* G  = (unsigned*)(smem + OFF_GUIDE);
    float*    Ek = smem + OFF_E;

    const int b   = blockIdx.y;
    const int tid = threadIdx.x;
    const int l8  = tid & (REP - 1);

    for (int idx = tid; idx < (K + 1) * REP; idx += 256) {
        const int s = idx / REP, l = idx % REP;
        const float2 v = g_seg2[b][s];
        SL[s * REP + l] = v.x;
        OF[s * REP + l] = v.y;
    }
    for (int i = tid; i < BINS; i += 256) G[i] = g_guide[i];
    for (int i = tid; i < K;    i += 256) Ek[i] = E[i];
    __syncthreads();

    const long long base = (long long)b * (long long)npix;
    const float4* __restrict__ in4  = (const float4*)(img + base);
    float4*       __restrict__ out4 = (float4*)(out + base);

    const int n4     = npix >> 2;
    const int stride = GRIDX * 256;
    int i = blockIdx.x * 256 + tid;

    // 4x unrolled (R6-proven shape at 64 warps/SM)
    for (; i + 3 * stride < n4; i += 4 * stride) {
        float4 xa[4];
        #pragma unroll
        for (int u = 0; u < 4; u++) xa[u] = in4[i + u * stride];
        #pragma unroll
        for (int u = 0; u < 4; u++) {
            float4 y;
            y.x = interp1(xa[u].x, l8, G, SL, OF, Ek, K);
            y.y = interp1(xa[u].y, l8, G, SL, OF, Ek, K);
            y.z = interp1(xa[u].z, l8, G, SL, OF, Ek, K);
            y.w = interp1(xa[u].w, l8, G, SL, OF, Ek, K);
            out4[i + u * stride] = y;
        }
    }
    for (; i < n4; i += stride) {
        const float4 x = in4[i];
        float4 y;
        y.x = interp1(x.x, l8, G, SL, OF, Ek, K);
        y.y = interp1(x.y, l8, G, SL, OF, Ek, K);
        y.z = interp1(x.z, l8, G, SL, OF, Ek, K);
        y.w = interp1(x.w, l8, G, SL, OF, Ek, K);
        out4[i] = y;
    }

    // scalar tail (npix not divisible by 4; empty for this shape)
    if (blockIdx.x == 0) {
        for (int tix = (n4 << 2) + tid; tix < npix; tix += 256)
            out[base + tix] = interp1(img[base + tix], l8, G, SL, OF, Ek, K);
    }
}

// ---------------------------------------------------------------------------
// Inputs (metadata order): hdr_image [B,C,H,W] f32, weights_w [B,NB] f32,
//                          E_samples [K] f32, f0_mean [K] f32, H_basis [K,NB] f32
// Output: [B,C,H,W] f32
// ---------------------------------------------------------------------------
extern "C" void kernel_launch(void* const* d_in, const int* in_sizes, int n_in,
                              void* d_out, int out_size)
{
    const float* img = (const float*)d_in[0];
    const float* w   = (const float*)d_in[1];
    const float* E   = (const float*)d_in[2];
    const float* f0  = (const float*)d_in[3];
    const float* Hb  = (const float*)d_in[4];
    float* out = (float*)d_out;

    const int K    = in_sizes[2];                 // 256
    const int NB   = in_sizes[4] / K;             // 25
    const int B    = in_sizes[1] / NB;            // 8
    const int npix = in_sizes[0] / B;             // C*H*W = 6,220,800

    const size_t smem_bytes = (size_t)SMEM_WORDS * 4;   // 26,112 B
    (void)cudaFuncSetAttribute(tmo_apply,
                               cudaFuncAttributeMaxDynamicSharedMemorySize,
                               (int)smem_bytes);

    setup_tables<<<B + GBLK, 256>>>(w, E, f0, Hb, K, NB, B);

    dim3 grid(GRIDX, B);                          // 1216 CTAs = 8/SM
    tmo_apply<<<grid, 256, smem_bytes>>>(img, out, E, npix, K);
}